// round 14
// baseline (speedup 1.0000x reference)
#include <cuda_runtime.h>
#include <cuda_bf16.h>
#include <math.h>
#include <stdint.h>

#define BB 8
#define CC 256
#define CI 128
#define NN 4096
#define MM 1024
#define NTOT (BB * NN)   // 32768 rows of y

// ---------------- device-global scratch (no allocation allowed) ---------------
__device__ __align__(16) __nv_bfloat16 g_xT_hi[(long)BB * NN * CC];
__device__ __align__(16) __nv_bfloat16 g_xT_lo[(long)BB * NN * CC];
__device__ __align__(16) __nv_bfloat16 g_w_hi[384 * CC + CC * CI];
__device__ __align__(16) __nv_bfloat16 g_w_lo[384 * CC + CC * CI];
__device__ float g_bias384[384];
__device__ __align__(16) __nv_bfloat16 g_o3_hi[(long)BB * NN * 384];
__device__ __align__(16) __nv_bfloat16 g_o3_lo[(long)BB * NN * 384];
__device__ __align__(16) __nv_bfloat16 g_phi_hi[(long)BB * MM * CI];  // [b][m][ci]
__device__ __align__(16) __nv_bfloat16 g_phi_lo[(long)BB * MM * CI];
__device__ __align__(16) __nv_bfloat16 g_gm_hi[(long)BB * MM * CI];   // [b][m][ci]
__device__ __align__(16) __nv_bfloat16 g_gm_lo[(long)BB * MM * CI];
__device__ __align__(16) __nv_bfloat16 g_y_hi[(long)NTOT * CI];
__device__ __align__(16) __nv_bfloat16 g_y_lo[(long)NTOT * CI];
__device__ float  g_mpart[64 * CI * CI];    // per-CTA partials of Y^T Y
__device__ float  g_yspart[128 * 256];      // ysum partials
__device__ double g_mred[CI * CI];          // reduced Y^T Y
__device__ float  g_scale[CC], g_shift[CC];

#define SWZ128(off) ((uint32_t)(off) ^ (((uint32_t)(off) >> 3) & 0x70))
#define SWZ256(off) ((uint32_t)(off) ^ (((uint32_t)(off) >> 4) & 0x70))

// ---------------- PTX wrappers ------------------------------------------------
__device__ __forceinline__ uint32_t smem_u32(const void* p) {
    uint32_t a;
    asm("{ .reg .u64 t; cvta.to.shared.u64 t, %1; cvt.u32.u64 %0, t; }" : "=r"(a) : "l"(p));
    return a;
}
#define LDSM_X4(r0, r1, r2, r3, addr) \
    asm volatile("ldmatrix.sync.aligned.m8n8.x4.shared.b16 {%0,%1,%2,%3}, [%4];" \
                 : "=r"(r0), "=r"(r1), "=r"(r2), "=r"(r3) : "r"(addr))
#define LDSM_X4_T(r0, r1, r2, r3, addr) \
    asm volatile("ldmatrix.sync.aligned.m8n8.x4.trans.shared.b16 {%0,%1,%2,%3}, [%4];" \
                 : "=r"(r0), "=r"(r1), "=r"(r2), "=r"(r3) : "r"(addr))
__device__ __forceinline__ void mma16816(float* c, uint32_t a0, uint32_t a1, uint32_t a2, uint32_t a3,
                                         uint32_t b0, uint32_t b1) {
    asm volatile(
        "mma.sync.aligned.m16n8k16.row.col.f32.bf16.bf16.f32 "
        "{%0,%1,%2,%3}, {%4,%5,%6,%7}, {%8,%9}, {%0,%1,%2,%3};"
        : "+f"(c[0]), "+f"(c[1]), "+f"(c[2]), "+f"(c[3])
        : "r"(a0), "r"(a1), "r"(a2), "r"(a3), "r"(b0), "r"(b1));
}
__device__ __forceinline__ void cpa16(uint32_t dst, const void* src) {
    asm volatile("cp.async.cg.shared.global [%0], [%1], 16;" :: "r"(dst), "l"(src));
}
#define CP_COMMIT() asm volatile("cp.async.commit_group;")
#define CP_WAIT0()  asm volatile("cp.async.wait_group 0;")

__device__ __forceinline__ void split2(float v, __nv_bfloat16& h, __nv_bfloat16& l) {
    h = __float2bfloat16(v);
    l = __float2bfloat16(v - __bfloat162float(h));
}
__device__ __forceinline__ uint32_t pk2(float e, float o) {
    __nv_bfloat162 v(__float2bfloat16(e), __float2bfloat16(o));
    return *(uint32_t*)&v;
}

// =====================  bf16 hi/lo pipelined tensor-core GEMM  ================
#define STAGE_BYTES 65536
#define SMEM_GEMM_BYTES (2 * STAGE_BYTES)

__device__ __forceinline__ void load_op(const __nv_bfloat16* hi, const __nv_bfloat16* lo,
                                        int rowBase, int ld, int k0,
                                        uint32_t smH, uint32_t smL, int tid) {
    #pragma unroll
    for (int it = 0; it < 4; it++) {
        int idx = it * 256 + tid;
        int r = idx >> 3, s = idx & 7;
        uint32_t sw = SWZ128(r * 128 + s * 16);
        cpa16(smH + sw, hi + (long)(rowBase + r) * ld + k0 + s * 8);
        cpa16(smL + sw, lo + (long)(rowBase + r) * ld + k0 + s * 8);
    }
}

// BIAS_MODE: 0 none, 2 per-col. OUT_MODE: 0 fp32, 1 bf16 hi/lo, 2 final BN+residual.
template<int BIAS_MODE, int OUT_MODE>
__global__ __launch_bounds__(256) void gemm_bf16(
    const __nv_bfloat16* __restrict__ Ahi, const __nv_bfloat16* __restrict__ Alo,
    const __nv_bfloat16* __restrict__ Bhi, const __nv_bfloat16* __restrict__ Blo,
    const float* __restrict__ bias,
    float* __restrict__ Cf, __nv_bfloat16* __restrict__ Chi, __nv_bfloat16* __restrict__ Clo,
    const float* __restrict__ xin,
    int ldA, int ldB, int ldC, int K,
    long sA, long sB, long sC)
{
    extern __shared__ __align__(1024) char sm[];
    const int bz = blockIdx.z;
    Ahi += (long)bz * sA; Alo += (long)bz * sA;
    Bhi += (long)bz * sB; Blo += (long)bz * sB;
    const long coff = (long)bz * sC;

    const int mBlock = blockIdx.y * 128;
    const int nBlock = blockIdx.x * 128;
    const int tid = threadIdx.x;
    const int wid = tid >> 5;
    const int lane = tid & 31;
    const uint32_t sbase = smem_u32(sm);

    const int mWarp = (wid >> 2) * 64;
    const int nWarp = (wid & 3) * 32;

    float acc[4][4][4];
    #pragma unroll
    for (int i = 0; i < 4; i++)
        #pragma unroll
        for (int j = 0; j < 4; j++)
            #pragma unroll
            for (int r = 0; r < 4; r++) acc[i][j][r] = 0.f;

    const int aRow = mWarp + (lane & 15);
    const int aKb  = (lane >> 4) << 4;
    const int bR16 = (lane & 7) + ((lane >> 4) & 1) * 8;
    const int bKb  = ((lane >> 3) & 1) << 4;

    const int nChunks = K >> 6;
    load_op(Ahi, Alo, mBlock, ldA, 0, sbase + 0,     sbase + 16384, tid);
    load_op(Bhi, Blo, nBlock, ldB, 0, sbase + 32768, sbase + 49152, tid);
    CP_COMMIT();

    for (int ch = 0; ch < nChunks; ch++) {
        CP_WAIT0();
        __syncthreads();
        if (ch + 1 < nChunks) {
            const uint32_t sb = sbase + ((ch + 1) & 1) * STAGE_BYTES;
            const int k0 = (ch + 1) << 6;
            load_op(Ahi, Alo, mBlock, ldA, k0, sb + 0,     sb + 16384, tid);
            load_op(Bhi, Blo, nBlock, ldB, k0, sb + 32768, sb + 49152, tid);
            CP_COMMIT();
        }

        const uint32_t st = sbase + (ch & 1) * STAGE_BYTES;
        #pragma unroll
        for (int ks = 0; ks < 4; ks++) {
            uint32_t aH[4][4], aL[4][4];
            #pragma unroll
            for (int mi = 0; mi < 4; mi++) {
                uint32_t sw = SWZ128((aRow + mi * 16) * 128 + ks * 32 + aKb);
                LDSM_X4(aH[mi][0], aH[mi][1], aH[mi][2], aH[mi][3], st + 0 + sw);
                LDSM_X4(aL[mi][0], aL[mi][1], aL[mi][2], aL[mi][3], st + 16384 + sw);
            }
            #pragma unroll
            for (int np = 0; np < 2; np++) {
                uint32_t sw = SWZ128((nWarp + np * 16 + bR16) * 128 + ks * 32 + bKb);
                uint32_t bh0, bh1, bh2, bh3, bl0, bl1, bl2, bl3;
                LDSM_X4(bh0, bh1, bh2, bh3, st + 32768 + sw);
                LDSM_X4(bl0, bl1, bl2, bl3, st + 49152 + sw);
                #pragma unroll
                for (int mi = 0; mi < 4; mi++) {
                    mma16816(acc[mi][2 * np], aH[mi][0], aH[mi][1], aH[mi][2], aH[mi][3], bh0, bh1);
                    mma16816(acc[mi][2 * np], aH[mi][0], aH[mi][1], aH[mi][2], aH[mi][3], bl0, bl1);
                    mma16816(acc[mi][2 * np], aL[mi][0], aL[mi][1], aL[mi][2], aL[mi][3], bh0, bh1);
                    mma16816(acc[mi][2 * np + 1], aH[mi][0], aH[mi][1], aH[mi][2], aH[mi][3], bh2, bh3);
                    mma16816(acc[mi][2 * np + 1], aH[mi][0], aH[mi][1], aH[mi][2], aH[mi][3], bl2, bl3);
                    mma16816(acc[mi][2 * np + 1], aL[mi][0], aL[mi][1], aL[mi][2], aL[mi][3], bh2, bh3);
                }
            }
        }
    }

    const int mLane = lane >> 2;
    const int nLane = (lane & 3) * 2;
    #pragma unroll
    for (int mi = 0; mi < 4; mi++) {
        const int m0 = mBlock + mWarp + mi * 16 + mLane;
        float sc0 = 0.f, sh0 = 0.f, sc1 = 0.f, sh1 = 0.f;
        if (OUT_MODE == 2) {
            sc0 = g_scale[m0]; sh0 = g_shift[m0];
            sc1 = g_scale[m0 + 8]; sh1 = g_shift[m0 + 8];
        }
        #pragma unroll
        for (int ni = 0; ni < 4; ni++) {
            const int n = nBlock + nWarp + ni * 8 + nLane;
            float c0 = acc[mi][ni][0], c1 = acc[mi][ni][1];
            float c2 = acc[mi][ni][2], c3 = acc[mi][ni][3];
            if (BIAS_MODE == 2) {
                float bx = bias[n], by = bias[n + 1];
                c0 += bx; c1 += by; c2 += bx; c3 += by;
            }
            if (OUT_MODE == 1) {
                __nv_bfloat16 h0, h1, h2, h3, l0, l1, l2, l3;
                split2(c0, h0, l0); split2(c1, h1, l1);
                split2(c2, h2, l2); split2(c3, h3, l3);
                *(__nv_bfloat162*)&Chi[coff + (long)m0 * ldC + n]       = __nv_bfloat162(h0, h1);
                *(__nv_bfloat162*)&Clo[coff + (long)m0 * ldC + n]       = __nv_bfloat162(l0, l1);
                *(__nv_bfloat162*)&Chi[coff + (long)(m0 + 8) * ldC + n] = __nv_bfloat162(h2, h3);
                *(__nv_bfloat162*)&Clo[coff + (long)(m0 + 8) * ldC + n] = __nv_bfloat162(l2, l3);
            } else if (OUT_MODE == 2) {
                const long i0 = coff + (long)m0 * ldC + n;
                const long i1 = coff + (long)(m0 + 8) * ldC + n;
                float2 x0 = *(const float2*)&xin[i0];
                float2 x1 = *(const float2*)&xin[i1];
                float2 v0, v1;
                v0.x = fmaf(c0, sc0, sh0) + x0.x;
                v0.y = fmaf(c1, sc0, sh0) + x0.y;
                v1.x = fmaf(c2, sc1, sh1) + x1.x;
                v1.y = fmaf(c3, sc1, sh1) + x1.y;
                *(float2*)&Cf[i0] = v0;
                *(float2*)&Cf[i1] = v1;
            } else {
                float2 v0 = {c0, c1}, v1 = {c2, c3};
                *(float2*)&Cf[coff + (long)m0 * ldC + n]       = v0;
                *(float2*)&Cf[coff + (long)(m0 + 8) * ldC + n] = v1;
            }
        }
    }
}

// =====================  fused attention (2 CTAs/SM, no-max softmax)  ==========
#define ATT_SMEM (32768 + 2 * 32768)
#define ATT_STAGE 32768

__device__ __forceinline__ void att_load_chunk(int b, int m0, uint32_t buf, int tid) {
    const __nv_bfloat16* ph = g_phi_hi + ((long)b * MM + m0) * CI;
    const __nv_bfloat16* pl = g_phi_lo + ((long)b * MM + m0) * CI;
    const __nv_bfloat16* gh = g_gm_hi + ((long)b * MM + m0) * CI;
    const __nv_bfloat16* gl = g_gm_lo + ((long)b * MM + m0) * CI;
    #pragma unroll
    for (int it = 0; it < 4; it++) {
        int idx = it * 128 + tid;       // 512: r(32) x s(16)
        int r = idx >> 4, s = idx & 15;
        uint32_t sw = SWZ256(r * 256 + s * 16);
        cpa16(buf + 0 + sw,     ph + (long)r * CI + s * 8);
        cpa16(buf + 8192 + sw,  pl + (long)r * CI + s * 8);
        cpa16(buf + 16384 + sw, gh + (long)r * CI + s * 8);
        cpa16(buf + 24576 + sw, gl + (long)r * CI + s * 8);
    }
}

__global__ __launch_bounds__(128, 2) void attn_kernel() {
    extern __shared__ __align__(1024) char sm[];
    const int b = blockIdx.y;
    const int nBlock = blockIdx.x * 64;
    const int tid = threadIdx.x;
    const int wid = tid >> 5;
    const int lane = tid & 31;
    const uint32_t sbase = smem_u32(sm);
    const uint32_t TH = 0, TL = 16384, BUF0 = 32768;

    {
        const __nv_bfloat16* th = g_o3_hi + ((long)b * NN + nBlock) * 384;
        const __nv_bfloat16* tl = g_o3_lo + ((long)b * NN + nBlock) * 384;
        #pragma unroll
        for (int it = 0; it < 8; it++) {
            int idx = it * 128 + tid;   // 1024: r(64) x s(16)
            int r = idx >> 4, s = idx & 15;
            uint32_t sw = SWZ256(r * 256 + s * 16);
            cpa16(sbase + TH + sw, th + (long)r * 384 + s * 8);
            cpa16(sbase + TL + sw, tl + (long)r * 384 + s * 8);
        }
    }
    att_load_chunk(b, 0, sbase + BUF0, tid);
    CP_COMMIT();

    const int aRowOff = wid * 16 + (lane & 15);
    const uint32_t aKb = (lane >> 4) << 4;
    const int bR = (lane & 7) + ((lane >> 4) & 1) * 8;
    const uint32_t bKb = ((lane >> 3) & 1) << 4;
    const int gRow = (lane & 7) + ((lane >> 3) & 1) * 8;
    const int gCol = (lane >> 4);

    float yacc[16][4];
    #pragma unroll
    for (int t = 0; t < 16; t++)
        #pragma unroll
        for (int r = 0; r < 4; r++) yacc[t][r] = 0.f;
    float rl0 = 0.f, rl1 = 0.f;

    for (int ch = 0; ch < 32; ch++) {
        CP_WAIT0();
        __syncthreads();
        if (ch < 31) {
            att_load_chunk(b, (ch + 1) * 32, sbase + BUF0 + ((ch + 1) & 1) * ATT_STAGE, tid);
            CP_COMMIT();
        }
        const uint32_t bs = sbase + BUF0 + (ch & 1) * ATT_STAGE;

        float sacc[4][4];
        #pragma unroll
        for (int j = 0; j < 4; j++)
            #pragma unroll
            for (int r = 0; r < 4; r++) sacc[j][r] = 0.f;

        #pragma unroll
        for (int ks = 0; ks < 8; ks++) {
            uint32_t aH0, aH1, aH2, aH3, aL0, aL1, aL2, aL3;
            uint32_t swA = SWZ256(aRowOff * 256 + ks * 32 + aKb);
            LDSM_X4(aH0, aH1, aH2, aH3, sbase + TH + swA);
            LDSM_X4(aL0, aL1, aL2, aL3, sbase + TL + swA);
            #pragma unroll
            for (int jp = 0; jp < 2; jp++) {
                uint32_t swB = SWZ256((jp * 16 + bR) * 256 + ks * 32 + bKb);
                uint32_t bh0, bh1, bh2, bh3, bl0, bl1, bl2, bl3;
                LDSM_X4(bh0, bh1, bh2, bh3, bs + 0 + swB);
                LDSM_X4(bl0, bl1, bl2, bl3, bs + 8192 + swB);
                mma16816(sacc[2 * jp],     aH0, aH1, aH2, aH3, bh0, bh1);
                mma16816(sacc[2 * jp],     aH0, aH1, aH2, aH3, bl0, bl1);
                mma16816(sacc[2 * jp],     aL0, aL1, aL2, aL3, bh0, bh1);
                mma16816(sacc[2 * jp + 1], aH0, aH1, aH2, aH3, bh2, bh3);
                mma16816(sacc[2 * jp + 1], aH0, aH1, aH2, aH3, bl2, bl3);
                mma16816(sacc[2 * jp + 1], aL0, aL1, aL2, aL3, bh2, bh3);
            }
        }

        uint32_t pH[4][2], pL[4][2];
        #pragma unroll
        for (int j = 0; j < 4; j++) {
            float e0 = __expf(sacc[j][0]);
            float e1 = __expf(sacc[j][1]);
            float e2 = __expf(sacc[j][2]);
            float e3 = __expf(sacc[j][3]);
            rl0 += e0 + e1; rl1 += e2 + e3;
            float h0 = __bfloat162float(__float2bfloat16(e0));
            float h1 = __bfloat162float(__float2bfloat16(e1));
            float h2 = __bfloat162float(__float2bfloat16(e2));
            float h3 = __bfloat162float(__float2bfloat16(e3));
            pH[j][0] = pk2(e0, e1);
            pH[j][1] = pk2(e2, e3);
            pL[j][0] = pk2(e0 - h0, e1 - h1);
            pL[j][1] = pk2(e2 - h2, e3 - h3);
        }

        #pragma unroll
        for (int kk = 0; kk < 2; kk++) {
            const uint32_t ah0 = pH[2 * kk][0], ah1 = pH[2 * kk][1];
            const uint32_t ah2 = pH[2 * kk + 1][0], ah3 = pH[2 * kk + 1][1];
            const uint32_t al0r = pL[2 * kk][0], al1r = pL[2 * kk][1];
            const uint32_t al2r = pL[2 * kk + 1][0], al3r = pL[2 * kk + 1][1];
            #pragma unroll
            for (int t2 = 0; t2 < 8; t2++) {
                uint32_t swG = SWZ256((kk * 16 + gRow) * 256 + (2 * t2 + gCol) * 16);
                uint32_t gh0, gh1, gh2, gh3, gl0, gl1, gl2, gl3;
                LDSM_X4_T(gh0, gh1, gh2, gh3, bs + 16384 + swG);
                LDSM_X4_T(gl0, gl1, gl2, gl3, bs + 24576 + swG);
                mma16816(yacc[2 * t2],     ah0, ah1, ah2, ah3, gh0, gh1);
                mma16816(yacc[2 * t2],     ah0, ah1, ah2, ah3, gl0, gl1);
                mma16816(yacc[2 * t2],     al0r, al1r, al2r, al3r, gh0, gh1);
                mma16816(yacc[2 * t2 + 1], ah0, ah1, ah2, ah3, gh2, gh3);
                mma16816(yacc[2 * t2 + 1], ah0, ah1, ah2, ah3, gl2, gl3);
                mma16816(yacc[2 * t2 + 1], al0r, al1r, al2r, al3r, gh2, gh3);
            }
        }
    }

    rl0 += __shfl_xor_sync(0xffffffffu, rl0, 1);
    rl0 += __shfl_xor_sync(0xffffffffu, rl0, 2);
    rl1 += __shfl_xor_sync(0xffffffffu, rl1, 1);
    rl1 += __shfl_xor_sync(0xffffffffu, rl1, 2);
    const float inv0 = 1.f / rl0;
    const float inv1 = 1.f / rl1;
    const int n0 = nBlock + wid * 16 + (lane >> 2);
    const int cB = (lane & 3) * 2;
    #pragma unroll
    for (int t = 0; t < 16; t++) {
        const int ci = t * 8 + cB;
        float c0 = yacc[t][0] * inv0, c1 = yacc[t][1] * inv0;
        float c2 = yacc[t][2] * inv1, c3 = yacc[t][3] * inv1;
        __nv_bfloat16 h0, h1, h2, h3, l0, l1, l2, l3;
        split2(c0, h0, l0); split2(c1, h1, l1);
        split2(c2, h2, l2); split2(c3, h3, l3);
        const long o0 = ((long)b * NN + n0) * CI + ci;
        const long o1 = ((long)b * NN + n0 + 8) * CI + ci;
        *(__nv_bfloat162*)&g_y_hi[o0] = __nv_bfloat162(h0, h1);
        *(__nv_bfloat162*)&g_y_lo[o0] = __nv_bfloat162(l0, l1);
        *(__nv_bfloat162*)&g_y_hi[o1] = __nv_bfloat162(h2, h3);
        *(__nv_bfloat162*)&g_y_lo[o1] = __nv_bfloat162(l2, l3);
    }
}

// =====================  ymom: M = Y^T Y partials (split-K, 64 CTAs)  ==========
// Y = y hi/lo [NTOT][128]. Each CTA: 512 rows in 8 chunks of 64.
// 3-term: M ~ hh + hl + lh (symmetric; ll term ~2^-32, negligible).
#define YMOM_STAGE 32768
#define YMOM_SMEM (2 * YMOM_STAGE)

__global__ __launch_bounds__(256) void ymom_kernel() {
    extern __shared__ __align__(1024) char sm[];
    const int cta = blockIdx.x;
    const int rowBase = cta * 512;
    const int tid = threadIdx.x;
    const int wid = tid >> 5;
    const int lane = tid & 31;
    const uint32_t sbase = smem_u32(sm);

    const int mWarp = (wid >> 2) * 64;   // ci block
    const int nWarp = (wid & 3) * 32;    // cj block

    float acc[4][4][4];
    #pragma unroll
    for (int i = 0; i < 4; i++)
        #pragma unroll
        for (int j = 0; j < 4; j++)
            #pragma unroll
            for (int r = 0; r < 4; r++) acc[i][j][r] = 0.f;

    // trans-A lane pattern: row(n) = (lane&7) + bit4*8 ; col16B(ci-half) = bit3
    const int aRowT = (lane & 7) + ((lane >> 4) & 1) * 8;
    const int aC16  = (lane >> 3) & 1;
    // trans-B lane pattern: row(n) = (lane&7) + bit3*8 ; col16B(cj group) = bit4
    const int bRowT = (lane & 7) + ((lane >> 3) & 1) * 8;
    const int bC16  = (lane >> 4);

    // prologue load chunk 0
    {
        const __nv_bfloat16* yh = g_y_hi + (long)rowBase * CI;
        const __nv_bfloat16* yl = g_y_lo + (long)rowBase * CI;
        #pragma unroll
        for (int it = 0; it < 4; it++) {
            int idx = it * 256 + tid;   // 1024: r(64) x s(16)
            int r = idx >> 4, s = idx & 15;
            uint32_t sw = SWZ256(r * 256 + s * 16);
            cpa16(sbase + 0 + sw,     yh + (long)r * CI + s * 8);
            cpa16(sbase + 16384 + sw, yl + (long)r * CI + s * 8);
        }
    }
    CP_COMMIT();

    for (int ch = 0; ch < 8; ch++) {
        CP_WAIT0();
        __syncthreads();
        if (ch < 7) {
            const uint32_t sb = sbase + ((ch + 1) & 1) * YMOM_STAGE;
            const __nv_bfloat16* yh = g_y_hi + (long)(rowBase + (ch + 1) * 64) * CI;
            const __nv_bfloat16* yl = g_y_lo + (long)(rowBase + (ch + 1) * 64) * CI;
            #pragma unroll
            for (int it = 0; it < 4; it++) {
                int idx = it * 256 + tid;
                int r = idx >> 4, s = idx & 15;
                uint32_t sw = SWZ256(r * 256 + s * 16);
                cpa16(sb + 0 + sw,     yh + (long)r * CI + s * 8);
                cpa16(sb + 16384 + sw, yl + (long)r * CI + s * 8);
            }
            CP_COMMIT();
        }
        const uint32_t st = sbase + (ch & 1) * YMOM_STAGE;

        #pragma unroll
        for (int ks = 0; ks < 4; ks++) {     // 4 n16 steps within 64-row chunk
            uint32_t aH[4][4], aL[4][4];
            #pragma unroll
            for (int mi = 0; mi < 4; mi++) {
                uint32_t sw = SWZ256((ks * 16 + aRowT) * 256 + (mWarp + mi * 16) * 2 + aC16 * 16);
                LDSM_X4_T(aH[mi][0], aH[mi][1], aH[mi][2], aH[mi][3], st + 0 + sw);
                LDSM_X4_T(aL[mi][0], aL[mi][1], aL[mi][2], aL[mi][3], st + 16384 + sw);
            }
            #pragma unroll
            for (int jp = 0; jp < 2; jp++) {
                uint32_t sw = SWZ256((ks * 16 + bRowT) * 256 + (nWarp + jp * 16) * 2 + bC16 * 16);
                uint32_t bh0, bh1, bh2, bh3, bl0, bl1, bl2, bl3;
                LDSM_X4_T(bh0, bh1, bh2, bh3, st + 0 + sw);
                LDSM_X4_T(bl0, bl1, bl2, bl3, st + 16384 + sw);
                #pragma unroll
                for (int mi = 0; mi < 4; mi++) {
                    mma16816(acc[mi][2 * jp], aH[mi][0], aH[mi][1], aH[mi][2], aH[mi][3], bh0, bh1);
                    mma16816(acc[mi][2 * jp], aH[mi][0], aH[mi][1], aH[mi][2], aH[mi][3], bl0, bl1);
                    mma16816(acc[mi][2 * jp], aL[mi][0], aL[mi][1], aL[mi][2], aL[mi][3], bh0, bh1);
                    mma16816(acc[mi][2 * jp + 1], aH[mi][0], aH[mi][1], aH[mi][2], aH[mi][3], bh2, bh3);
                    mma16816(acc[mi][2 * jp + 1], aH[mi][0], aH[mi][1], aH[mi][2], aH[mi][3], bl2, bl3);
                    mma16816(acc[mi][2 * jp + 1], aL[mi][0], aL[mi][1], aL[mi][2], aL[mi][3], bh2, bh3);
                }
            }
        }
    }

    // write partials
    const int mLane = lane >> 2;
    const int nLane = (lane & 3) * 2;
    float* mp = g_mpart + (long)cta * CI * CI;
    #pragma unroll
    for (int mi = 0; mi < 4; mi++) {
        const int ci0 = mWarp + mi * 16 + mLane;
        #pragma unroll
        for (int j = 0; j < 4; j++) {
            const int cj = nWarp + j * 8 + nLane;
            float2 v0 = {acc[mi][j][0], acc[mi][j][1]};
            float2 v1 = {acc[mi][j][2], acc[mi][j][3]};
            *(float2*)&mp[ci0 * CI + cj]       = v0;
            *(float2*)&mp[(ci0 + 8) * CI + cj] = v1;
        }
    }
}

// ---------------- M partial reduce ----------------------------------------------
__global__ __launch_bounds__(256) void mreduce_kernel() {
    const int e = blockIdx.x * 256 + threadIdx.x;   // 16384 entries
    double s = 0.0;
    #pragma unroll 4
    for (int p = 0; p < 64; p++)
        s += (double)g_mpart[p * CI * CI + e];
    g_mred[e] = s;
}

// ---------------- ysum partials --------------------------------------------------
__global__ __launch_bounds__(256) void ysum_kernel() {
    const int cta = blockIdx.x;   // 128 CTAs x 256 rows
    const int t = threadIdx.x;
    const int ci = t & 127;
    const int ro = t >> 7;
    float s = 0.f;
    for (int r = ro; r < 256; r += 2) {
        const long idx = (long)(cta * 256 + r) * CI + ci;
        s += __bfloat162float(g_y_hi[idx]) + __bfloat162float(g_y_lo[idx]);
    }
    g_yspart[cta * 256 + t] = s;
}

// ---------------- per-channel BN stats (deterministic, double) -------------------
__global__ __launch_bounds__(128) void stats_kernel(
    const float* __restrict__ Ww, const float* __restrict__ Wb,
    const float* __restrict__ gamma, const float* __restrict__ beta)
{
    const int c = blockIdx.x;
    const int i = threadIdx.x;
    __shared__ double sw[128], red[128];

    const double wi = (double)Ww[c * CI + i];
    sw[i] = wi;

    // ybar_i
    double ys = 0.0;
    for (int p = 0; p < 128; p++)
        ys += (double)g_yspart[p * 256 + i] + (double)g_yspart[p * 256 + 128 + i];
    const double ybar = ys / (double)NTOT;
    __syncthreads();

    // t_i = sum_j M[i][j] w_j
    double ti = 0.0;
    #pragma unroll 4
    for (int j = 0; j < 128; j++)
        ti += g_mred[i * CI + j] * sw[j];

    // reduce wMw = sum_i w_i t_i  and  wyb = sum_i w_i ybar_i
    red[i] = wi * ti;
    __syncthreads();
    for (int st = 64; st; st >>= 1) {
        if (i < st) red[i] += red[i + st];
        __syncthreads();
    }
    double wMw = red[0];
    __syncthreads();
    red[i] = wi * ybar;
    __syncthreads();
    for (int st = 64; st; st >>= 1) {
        if (i < st) red[i] += red[i + st];
        __syncthreads();
    }
    if (i == 0) {
        const double wyb = red[0];
        const double var = wMw / (double)NTOT - wyb * wyb;
        const double scale = (double)gamma[c] / sqrt(var + 1e-5);
        // out = (v + Wb)*scale + beta - (wyb + Wb)*scale = v*scale + beta - wyb*scale
        g_scale[c] = (float)scale;
        g_shift[c] = (float)((double)beta[c] - wyb * scale);
    }
}

// ---------------- x transpose + hi/lo convert ----------------------------------
__global__ __launch_bounds__(256) void transpose_x(const float* __restrict__ x) {
    __shared__ float t[32][33];
    const int b = blockIdx.z;
    const int n0 = blockIdx.x * 32, c0 = blockIdx.y * 32;
    const int tx = threadIdx.x, ty = threadIdx.y;
    #pragma unroll
    for (int i = ty; i < 32; i += 8)
        t[i][tx] = x[((long)b * CC + c0 + i) * NN + n0 + tx];
    __syncthreads();
    #pragma unroll
    for (int i = ty; i < 32; i += 8) {
        float v = t[tx][i];
        __nv_bfloat16 h, l;
        split2(v, h, l);
        const long o = ((long)b * NN + n0 + i) * CC + c0 + tx;
        g_xT_hi[o] = h;
        g_xT_lo[o] = l;
    }
}

// ---------------- weight convert ------------------------------------------------
__global__ __launch_bounds__(256) void convert_w(
    const float* __restrict__ tw, const float* __restrict__ pw, const float* __restrict__ gw,
    const float* __restrict__ tb, const float* __restrict__ pb, const float* __restrict__ gb,
    const float* __restrict__ Ww)
{
    const int i = blockIdx.x * 256 + threadIdx.x;
    const int TOT1 = 384 * CC;
    const int TOT2 = TOT1 + CC * CI;
    if (i < TOT1) {
        int o = i / CC, c = i % CC;
        float v = (o < 128) ? tw[o * CC + c] : (o < 256) ? pw[(o - 128) * CC + c] : gw[(o - 256) * CC + c];
        __nv_bfloat16 h, l; split2(v, h, l);
        g_w_hi[i] = h; g_w_lo[i] = l;
    } else if (i < TOT2) {
        float v = Ww[i - TOT1];
        __nv_bfloat16 h, l; split2(v, h, l);
        g_w_hi[i] = h; g_w_lo[i] = l;
    }
    if (i < 384)
        g_bias384[i] = (i < 128) ? tb[i] : (i < 256) ? pb[i - 128] : gb[i - 256];
}

// ---------------- 2x2 maxpool (both outputs [m][ci], coalesced) -----------------
__device__ __forceinline__ void ld4bf(const __nv_bfloat16* p, float* out) {
    uint2 u = *(const uint2*)p;
    __nv_bfloat162 a = *(__nv_bfloat162*)&u.x;
    __nv_bfloat162 bq = *(__nv_bfloat162*)&u.y;
    out[0] = __bfloat162float(a.x); out[1] = __bfloat162float(a.y);
    out[2] = __bfloat162float(bq.x); out[3] = __bfloat162float(bq.y);
}

__global__ __launch_bounds__(256) void pool_kernel() {
    const int i = blockIdx.x * 256 + threadIdx.x;   // BB*MM*32
    if (i >= BB * MM * 32) return;
    const int c4 = (i & 31) << 2;
    const int m  = (i >> 5) & (MM - 1);
    const int b  = i >> 15;
    const int hp = m >> 5, wp = m & 31;
    const int n0 = hp * 128 + wp * 2;
    const long rb = (long)b * NN;
    const long o = ((long)b * MM + m) * CI + c4;

    #pragma unroll
    for (int which = 0; which < 2; which++) {
        const int col = (which == 0 ? 128 : 256) + c4;
        float mx[4] = {-1e30f, -1e30f, -1e30f, -1e30f};
        #pragma unroll
        for (int rr = 0; rr < 4; rr++) {
            const int n = n0 + (rr & 1) + (rr >> 1) * 64;
            const long base = (rb + n) * 384 + col;
            float vh[4], vl[4];
            ld4bf(&g_o3_hi[base], vh);
            ld4bf(&g_o3_lo[base], vl);
            #pragma unroll
            for (int e = 0; e < 4; e++) mx[e] = fmaxf(mx[e], vh[e] + vl[e]);
        }
        __nv_bfloat16 h[4], l[4];
        #pragma unroll
        for (int e = 0; e < 4; e++) split2(mx[e], h[e], l[e]);
        __nv_bfloat16* dh = (which == 0) ? g_phi_hi : g_gm_hi;
        __nv_bfloat16* dl = (which == 0) ? g_phi_lo : g_gm_lo;
        *(__nv_bfloat162*)&dh[o]     = __nv_bfloat162(h[0], h[1]);
        *(__nv_bfloat162*)&dh[o + 2] = __nv_bfloat162(h[2], h[3]);
        *(__nv_bfloat162*)&dl[o]     = __nv_bfloat162(l[0], l[1]);
        *(__nv_bfloat162*)&dl[o + 2] = __nv_bfloat162(l[2], l[3]);
    }
}

// ------------------------------------------------------------------------------
extern "C" void kernel_launch(void* const* d_in, const int* in_sizes, int n_in,
                              void* d_out, int out_size) {
    (void)in_sizes; (void)n_in; (void)out_size;
    const float* x     = (const float*)d_in[0];
    const float* tw    = (const float*)d_in[1];
    const float* tb    = (const float*)d_in[2];
    const float* pw    = (const float*)d_in[3];
    const float* pb    = (const float*)d_in[4];
    const float* gw    = (const float*)d_in[5];
    const float* gb    = (const float*)d_in[6];
    const float* Ww    = (const float*)d_in[7];
    const float* Wb    = (const float*)d_in[8];
    const float* gamma = (const float*)d_in[9];
    const float* beta  = (const float*)d_in[10];
    float* out = (float*)d_out;

    __nv_bfloat16 *xTh, *xTl, *wh, *wl, *o3h, *o3l, *yh, *yl;
    float *bias384;
    cudaGetSymbolAddress((void**)&xTh, g_xT_hi);  cudaGetSymbolAddress((void**)&xTl, g_xT_lo);
    cudaGetSymbolAddress((void**)&wh,  g_w_hi);   cudaGetSymbolAddress((void**)&wl,  g_w_lo);
    cudaGetSymbolAddress((void**)&o3h, g_o3_hi);  cudaGetSymbolAddress((void**)&o3l, g_o3_lo);
    cudaGetSymbolAddress((void**)&yh,  g_y_hi);   cudaGetSymbolAddress((void**)&yl,  g_y_lo);
    cudaGetSymbolAddress((void**)&bias384, g_bias384);

    cudaFuncSetAttribute(gemm_bf16<2, 1>, cudaFuncAttributeMaxDynamicSharedMemorySize, SMEM_GEMM_BYTES);
    cudaFuncSetAttribute(gemm_bf16<0, 2>, cudaFuncAttributeMaxDynamicSharedMemorySize, SMEM_GEMM_BYTES);
    cudaFuncSetAttribute(attn_kernel, cudaFuncAttributeMaxDynamicSharedMemorySize, ATT_SMEM);
    cudaFuncSetAttribute(ymom_kernel, cudaFuncAttributeMaxDynamicSharedMemorySize, YMOM_SMEM);

    // P1: convert weights + biases
    convert_w<<<(384 * CC + CC * CI + 255) / 256, 256>>>(tw, pw, gw, tb, pb, gb, Ww);
    // P2: transpose + convert x -> xT [b][n][c]
    transpose_x<<<dim3(NN / 32, CC / 32, BB), dim3(32, 8)>>>(x);

    // K1: o3[b][n][o<384] = xT[n][c] . wcat[o][c]  (col bias), out bf16 hi/lo
    gemm_bf16<2, 1><<<dim3(3, 32, BB), 256, SMEM_GEMM_BYTES>>>(
        xTh, xTl, wh, wl, bias384, nullptr, o3h, o3l, nullptr,
        CC, CC, 384, CC, (long)NN * CC, 0, (long)NN * 384);

    // K2: maxpool -> phi [m][ci], gm [m][ci]
    pool_kernel<<<(BB * MM * 32 + 255) / 256, 256>>>();

    // K3: fused theta.phi^T -> exp -> .g  ==> y [b][n][ci] bf16 hi/lo
    attn_kernel<<<dim3(NN / 64, BB), 128, ATT_SMEM>>>();

    // K4a: Y^T Y partials + ysum partials + reduce + analytic BN stats
    ymom_kernel<<<64, 256, YMOM_SMEM>>>();
    ysum_kernel<<<128, 256>>>();
    mreduce_kernel<<<64, 256>>>();
    stats_kernel<<<CC, 128>>>(Ww, Wb, gamma, beta);

    // K4: out[b][c][n] = (Ww[c][ci].y[n][ci]) * scale[c] + shift[c] + x
    gemm_bf16<0, 2><<<dim3(NN / 128, CC / 128, BB), 256, SMEM_GEMM_BYTES>>>(
        wh + 384 * CC, wl + 384 * CC, yh, yl, nullptr, out, nullptr, nullptr, x,
        CI, CI, NN, CI, 0, (long)NN * CI, (long)CC * NN);
}

// round 17
// speedup vs baseline: 1.3195x; 1.3195x over previous
#include <cuda_runtime.h>
#include <cuda_bf16.h>
#include <math.h>
#include <stdint.h>

#define BB 8
#define CC 256
#define CI 128
#define NN 4096
#define MM 1024

// ---------------- device-global scratch (no allocation allowed) ---------------
__device__ __align__(16) __nv_bfloat16 g_xT_hi[(long)BB * NN * CC];
__device__ __align__(16) __nv_bfloat16 g_xT_lo[(long)BB * NN * CC];
__device__ __align__(16) __nv_bfloat16 g_w_hi[384 * CC + CC * CI];
__device__ __align__(16) __nv_bfloat16 g_w_lo[384 * CC + CC * CI];
__device__ float g_bias384[384];
__device__ __align__(16) __nv_bfloat16 g_o3_hi[(long)BB * NN * 384];
__device__ __align__(16) __nv_bfloat16 g_o3_lo[(long)BB * NN * 384];
__device__ __align__(16) __nv_bfloat16 g_phi_hi[(long)BB * MM * CI];  // [b][m][ci]
__device__ __align__(16) __nv_bfloat16 g_phi_lo[(long)BB * MM * CI];
__device__ __align__(16) __nv_bfloat16 g_gm_hi[(long)BB * MM * CI];   // [b][m][ci]
__device__ __align__(16) __nv_bfloat16 g_gm_lo[(long)BB * MM * CI];
__device__ __align__(16) __nv_bfloat16 g_y_hi[(long)BB * NN * CI];
__device__ __align__(16) __nv_bfloat16 g_y_lo[(long)BB * NN * CI];
__device__ float g_wy[(long)BB * CC * NN];
__device__ float g_part_s[CC * 1024];
__device__ float g_part_q[CC * 1024];
__device__ float g_scale[CC], g_shift[CC];

#define SWZ128(off) ((uint32_t)(off) ^ (((uint32_t)(off) >> 3) & 0x70))
#define SWZ256(off) ((uint32_t)(off) ^ (((uint32_t)(off) >> 4) & 0x70))

// ---------------- PTX wrappers ------------------------------------------------
__device__ __forceinline__ uint32_t smem_u32(const void* p) {
    uint32_t a;
    asm("{ .reg .u64 t; cvta.to.shared.u64 t, %1; cvt.u32.u64 %0, t; }" : "=r"(a) : "l"(p));
    return a;
}
#define LDSM_X4(r0, r1, r2, r3, addr) \
    asm volatile("ldmatrix.sync.aligned.m8n8.x4.shared.b16 {%0,%1,%2,%3}, [%4];" \
                 : "=r"(r0), "=r"(r1), "=r"(r2), "=r"(r3) : "r"(addr))
#define LDSM_X4_T(r0, r1, r2, r3, addr) \
    asm volatile("ldmatrix.sync.aligned.m8n8.x4.trans.shared.b16 {%0,%1,%2,%3}, [%4];" \
                 : "=r"(r0), "=r"(r1), "=r"(r2), "=r"(r3) : "r"(addr))
__device__ __forceinline__ void mma16816(float* c, uint32_t a0, uint32_t a1, uint32_t a2, uint32_t a3,
                                         uint32_t b0, uint32_t b1) {
    asm volatile(
        "mma.sync.aligned.m16n8k16.row.col.f32.bf16.bf16.f32 "
        "{%0,%1,%2,%3}, {%4,%5,%6,%7}, {%8,%9}, {%0,%1,%2,%3};"
        : "+f"(c[0]), "+f"(c[1]), "+f"(c[2]), "+f"(c[3])
        : "r"(a0), "r"(a1), "r"(a2), "r"(a3), "r"(b0), "r"(b1));
}
__device__ __forceinline__ void cpa16(uint32_t dst, const void* src) {
    asm volatile("cp.async.cg.shared.global [%0], [%1], 16;" :: "r"(dst), "l"(src));
}
#define CP_COMMIT() asm volatile("cp.async.commit_group;")
#define CP_WAIT0()  asm volatile("cp.async.wait_group 0;")

__device__ __forceinline__ void split2(float v, __nv_bfloat16& h, __nv_bfloat16& l) {
    h = __float2bfloat16(v);
    l = __float2bfloat16(v - __bfloat162float(h));
}
__device__ __forceinline__ uint32_t pk2(float e, float o) {
    __nv_bfloat162 v(__float2bfloat16(e), __float2bfloat16(o));
    return *(uint32_t*)&v;
}

// =====================  bf16 hi/lo pipelined tensor-core GEMM  ================
#define STAGE_BYTES 65536
#define SMEM_GEMM_BYTES (2 * STAGE_BYTES)

__device__ __forceinline__ void load_op(const __nv_bfloat16* hi, const __nv_bfloat16* lo,
                                        int rowBase, int ld, int k0,
                                        uint32_t smH, uint32_t smL, int tid) {
    #pragma unroll
    for (int it = 0; it < 4; it++) {
        int idx = it * 256 + tid;
        int r = idx >> 3, s = idx & 7;
        uint32_t sw = SWZ128(r * 128 + s * 16);
        cpa16(smH + sw, hi + (long)(rowBase + r) * ld + k0 + s * 8);
        cpa16(smL + sw, lo + (long)(rowBase + r) * ld + k0 + s * 8);
    }
}

// BIAS_MODE: 0 none, 1 per-row, 2 per-col. OUT_BF16 hi/lo out. PART: BN partials.
template<int BIAS_MODE, bool OUT_BF16, bool PART>
__global__ __launch_bounds__(256) void gemm_bf16(
    const __nv_bfloat16* __restrict__ Ahi, const __nv_bfloat16* __restrict__ Alo,
    const __nv_bfloat16* __restrict__ Bhi, const __nv_bfloat16* __restrict__ Blo,
    const float* __restrict__ bias,
    float* __restrict__ Cf, __nv_bfloat16* __restrict__ Chi, __nv_bfloat16* __restrict__ Clo,
    int ldA, int ldB, int ldC, int K,
    long sA, long sB, long sC)
{
    extern __shared__ __align__(1024) char sm[];
    const int bz = blockIdx.z;
    Ahi += (long)bz * sA; Alo += (long)bz * sA;
    Bhi += (long)bz * sB; Blo += (long)bz * sB;
    const long coff = (long)bz * sC;

    const int mBlock = blockIdx.y * 128;
    const int nBlock = blockIdx.x * 128;
    const int tid = threadIdx.x;
    const int wid = tid >> 5;
    const int lane = tid & 31;
    const uint32_t sbase = smem_u32(sm);

    const int mWarp = (wid >> 2) * 64;
    const int nWarp = (wid & 3) * 32;

    float acc[4][4][4];
    #pragma unroll
    for (int i = 0; i < 4; i++)
        #pragma unroll
        for (int j = 0; j < 4; j++)
            #pragma unroll
            for (int r = 0; r < 4; r++) acc[i][j][r] = 0.f;

    const int aRow = mWarp + (lane & 15);
    const int aKb  = (lane >> 4) << 4;
    const int bR16 = (lane & 7) + ((lane >> 4) & 1) * 8;
    const int bKb  = ((lane >> 3) & 1) << 4;

    const int nChunks = K >> 6;
    load_op(Ahi, Alo, mBlock, ldA, 0, sbase + 0,     sbase + 16384, tid);
    load_op(Bhi, Blo, nBlock, ldB, 0, sbase + 32768, sbase + 49152, tid);
    CP_COMMIT();

    for (int ch = 0; ch < nChunks; ch++) {
        CP_WAIT0();
        __syncthreads();
        if (ch + 1 < nChunks) {
            const uint32_t sb = sbase + ((ch + 1) & 1) * STAGE_BYTES;
            const int k0 = (ch + 1) << 6;
            load_op(Ahi, Alo, mBlock, ldA, k0, sb + 0,     sb + 16384, tid);
            load_op(Bhi, Blo, nBlock, ldB, k0, sb + 32768, sb + 49152, tid);
            CP_COMMIT();
        }

        const uint32_t st = sbase + (ch & 1) * STAGE_BYTES;
        #pragma unroll
        for (int ks = 0; ks < 4; ks++) {
            uint32_t aH[4][4], aL[4][4];
            #pragma unroll
            for (int mi = 0; mi < 4; mi++) {
                uint32_t sw = SWZ128((aRow + mi * 16) * 128 + ks * 32 + aKb);
                LDSM_X4(aH[mi][0], aH[mi][1], aH[mi][2], aH[mi][3], st + 0 + sw);
                LDSM_X4(aL[mi][0], aL[mi][1], aL[mi][2], aL[mi][3], st + 16384 + sw);
            }
            #pragma unroll
            for (int np = 0; np < 2; np++) {
                uint32_t sw = SWZ128((nWarp + np * 16 + bR16) * 128 + ks * 32 + bKb);
                uint32_t bh0, bh1, bh2, bh3, bl0, bl1, bl2, bl3;
                LDSM_X4(bh0, bh1, bh2, bh3, st + 32768 + sw);
                LDSM_X4(bl0, bl1, bl2, bl3, st + 49152 + sw);
                #pragma unroll
                for (int mi = 0; mi < 4; mi++) {
                    mma16816(acc[mi][2 * np], aH[mi][0], aH[mi][1], aH[mi][2], aH[mi][3], bh0, bh1);
                    mma16816(acc[mi][2 * np], aH[mi][0], aH[mi][1], aH[mi][2], aH[mi][3], bl0, bl1);
                    mma16816(acc[mi][2 * np], aL[mi][0], aL[mi][1], aL[mi][2], aL[mi][3], bh0, bh1);
                    mma16816(acc[mi][2 * np + 1], aH[mi][0], aH[mi][1], aH[mi][2], aH[mi][3], bh2, bh3);
                    mma16816(acc[mi][2 * np + 1], aH[mi][0], aH[mi][1], aH[mi][2], aH[mi][3], bl2, bl3);
                    mma16816(acc[mi][2 * np + 1], aL[mi][0], aL[mi][1], aL[mi][2], aL[mi][3], bh2, bh3);
                }
            }
        }
    }

    const int mLane = lane >> 2;
    const int nLane = (lane & 3) * 2;
    #pragma unroll
    for (int mi = 0; mi < 4; mi++) {
        const int m0 = mBlock + mWarp + mi * 16 + mLane;
        float br0 = 0.f, br1 = 0.f;
        if (BIAS_MODE == 1) { br0 = bias[m0]; br1 = bias[m0 + 8]; }
        float s0 = 0.f, q0 = 0.f, s1 = 0.f, q1 = 0.f;
        #pragma unroll
        for (int ni = 0; ni < 4; ni++) {
            const int n = nBlock + nWarp + ni * 8 + nLane;
            float c0 = acc[mi][ni][0], c1 = acc[mi][ni][1];
            float c2 = acc[mi][ni][2], c3 = acc[mi][ni][3];
            if (BIAS_MODE == 1) { c0 += br0; c1 += br0; c2 += br1; c3 += br1; }
            if (BIAS_MODE == 2) {
                float bx = bias[n], by = bias[n + 1];
                c0 += bx; c1 += by; c2 += bx; c3 += by;
            }
            if (PART) {
                s0 += c0 + c1; q0 += c0 * c0 + c1 * c1;
                s1 += c2 + c3; q1 += c2 * c2 + c3 * c3;
            }
            if (OUT_BF16) {
                __nv_bfloat16 h0, h1, h2, h3, l0, l1, l2, l3;
                split2(c0, h0, l0); split2(c1, h1, l1);
                split2(c2, h2, l2); split2(c3, h3, l3);
                *(__nv_bfloat162*)&Chi[coff + (long)m0 * ldC + n]       = __nv_bfloat162(h0, h1);
                *(__nv_bfloat162*)&Clo[coff + (long)m0 * ldC + n]       = __nv_bfloat162(l0, l1);
                *(__nv_bfloat162*)&Chi[coff + (long)(m0 + 8) * ldC + n] = __nv_bfloat162(h2, h3);
                *(__nv_bfloat162*)&Clo[coff + (long)(m0 + 8) * ldC + n] = __nv_bfloat162(l2, l3);
            } else {
                float2 v0 = {c0, c1}, v1 = {c2, c3};
                *(float2*)&Cf[coff + (long)m0 * ldC + n]       = v0;
                *(float2*)&Cf[coff + (long)(m0 + 8) * ldC + n] = v1;
            }
        }
        if (PART) {
            s0 += __shfl_xor_sync(0xffffffffu, s0, 1);
            s0 += __shfl_xor_sync(0xffffffffu, s0, 2);
            q0 += __shfl_xor_sync(0xffffffffu, q0, 1);
            q0 += __shfl_xor_sync(0xffffffffu, q0, 2);
            s1 += __shfl_xor_sync(0xffffffffu, s1, 1);
            s1 += __shfl_xor_sync(0xffffffffu, s1, 2);
            q1 += __shfl_xor_sync(0xffffffffu, q1, 1);
            q1 += __shfl_xor_sync(0xffffffffu, q1, 2);
            if ((lane & 3) == 0) {
                const int slot = (bz * 32 + blockIdx.x) * 4 + (wid & 3);
                g_part_s[m0 * 1024 + slot] = s0;
                g_part_q[m0 * 1024 + slot] = q0;
                g_part_s[(m0 + 8) * 1024 + slot] = s1;
                g_part_q[(m0 + 8) * 1024 + slot] = q1;
            }
        }
    }
}

// =====================  fused attention (2 CTAs/SM, no-max softmax)  ==========
// Theta fragments hoisted to registers (128-thr CTA: ~200 regs, no spill).
#define ATT_SMEM (32768 + 2 * 32768)
#define ATT_STAGE 32768

__device__ __forceinline__ void att_load_chunk(int b, int m0, uint32_t buf, int tid) {
    const __nv_bfloat16* ph = g_phi_hi + ((long)b * MM + m0) * CI;
    const __nv_bfloat16* pl = g_phi_lo + ((long)b * MM + m0) * CI;
    const __nv_bfloat16* gh = g_gm_hi + ((long)b * MM + m0) * CI;
    const __nv_bfloat16* gl = g_gm_lo + ((long)b * MM + m0) * CI;
    #pragma unroll
    for (int it = 0; it < 4; it++) {
        int idx = it * 128 + tid;       // 512: r(32) x s(16)
        int r = idx >> 4, s = idx & 15;
        uint32_t sw = SWZ256(r * 256 + s * 16);
        cpa16(buf + 0 + sw,     ph + (long)r * CI + s * 8);
        cpa16(buf + 8192 + sw,  pl + (long)r * CI + s * 8);
        cpa16(buf + 16384 + sw, gh + (long)r * CI + s * 8);
        cpa16(buf + 24576 + sw, gl + (long)r * CI + s * 8);
    }
}

__global__ __launch_bounds__(128, 2) void attn_kernel() {
    extern __shared__ __align__(1024) char sm[];
    const int b = blockIdx.y;
    const int nBlock = blockIdx.x * 64;
    const int tid = threadIdx.x;
    const int wid = tid >> 5;
    const int lane = tid & 31;
    const uint32_t sbase = smem_u32(sm);
    const uint32_t TH = 0, TL = 16384, BUF0 = 32768;

    {
        const __nv_bfloat16* th = g_o3_hi + ((long)b * NN + nBlock) * 384;
        const __nv_bfloat16* tl = g_o3_lo + ((long)b * NN + nBlock) * 384;
        #pragma unroll
        for (int it = 0; it < 8; it++) {
            int idx = it * 128 + tid;   // 1024: r(64) x s(16)
            int r = idx >> 4, s = idx & 15;
            uint32_t sw = SWZ256(r * 256 + s * 16);
            cpa16(sbase + TH + sw, th + (long)r * 384 + s * 8);
            cpa16(sbase + TL + sw, tl + (long)r * 384 + s * 8);
        }
    }
    att_load_chunk(b, 0, sbase + BUF0, tid);
    CP_COMMIT();
    CP_WAIT0();
    __syncthreads();

    const int aRowOff = wid * 16 + (lane & 15);
    const uint32_t aKb = (lane >> 4) << 4;
    const int bR = (lane & 7) + ((lane >> 4) & 1) * 8;
    const uint32_t bKb = ((lane >> 3) & 1) << 4;
    const int gRow = (lane & 7) + ((lane >> 3) & 1) * 8;
    const int gCol = (lane >> 4);

    // ---- hoist theta fragments (loaded once, reused for all 32 chunks) ----
    uint32_t thF[8][4], tlF[8][4];
    #pragma unroll
    for (int ks = 0; ks < 8; ks++) {
        uint32_t swA = SWZ256(aRowOff * 256 + ks * 32 + aKb);
        LDSM_X4(thF[ks][0], thF[ks][1], thF[ks][2], thF[ks][3], sbase + TH + swA);
        LDSM_X4(tlF[ks][0], tlF[ks][1], tlF[ks][2], tlF[ks][3], sbase + TL + swA);
    }

    float yacc[16][4];
    #pragma unroll
    for (int t = 0; t < 16; t++)
        #pragma unroll
        for (int r = 0; r < 4; r++) yacc[t][r] = 0.f;
    float rl0 = 0.f, rl1 = 0.f;

    for (int ch = 0; ch < 32; ch++) {
        if (ch) {
            CP_WAIT0();
            __syncthreads();
        }
        if (ch < 31) {
            att_load_chunk(b, (ch + 1) * 32, sbase + BUF0 + ((ch + 1) & 1) * ATT_STAGE, tid);
            CP_COMMIT();
        }
        const uint32_t bs = sbase + BUF0 + (ch & 1) * ATT_STAGE;

        float sacc[4][4];
        #pragma unroll
        for (int j = 0; j < 4; j++)
            #pragma unroll
            for (int r = 0; r < 4; r++) sacc[j][r] = 0.f;

        #pragma unroll
        for (int ks = 0; ks < 8; ks++) {
            #pragma unroll
            for (int jp = 0; jp < 2; jp++) {
                uint32_t swB = SWZ256((jp * 16 + bR) * 256 + ks * 32 + bKb);
                uint32_t bh0, bh1, bh2, bh3, bl0, bl1, bl2, bl3;
                LDSM_X4(bh0, bh1, bh2, bh3, bs + 0 + swB);
                LDSM_X4(bl0, bl1, bl2, bl3, bs + 8192 + swB);
                mma16816(sacc[2 * jp],     thF[ks][0], thF[ks][1], thF[ks][2], thF[ks][3], bh0, bh1);
                mma16816(sacc[2 * jp],     thF[ks][0], thF[ks][1], thF[ks][2], thF[ks][3], bl0, bl1);
                mma16816(sacc[2 * jp],     tlF[ks][0], tlF[ks][1], tlF[ks][2], tlF[ks][3], bh0, bh1);
                mma16816(sacc[2 * jp + 1], thF[ks][0], thF[ks][1], thF[ks][2], thF[ks][3], bh2, bh3);
                mma16816(sacc[2 * jp + 1], thF[ks][0], thF[ks][1], thF[ks][2], thF[ks][3], bl2, bl3);
                mma16816(sacc[2 * jp + 1], tlF[ks][0], tlF[ks][1], tlF[ks][2], tlF[ks][3], bh2, bh3);
            }
        }

        uint32_t pH[4][2], pL[4][2];
        #pragma unroll
        for (int j = 0; j < 4; j++) {
            float e0 = __expf(sacc[j][0]);
            float e1 = __expf(sacc[j][1]);
            float e2 = __expf(sacc[j][2]);
            float e3 = __expf(sacc[j][3]);
            rl0 += e0 + e1; rl1 += e2 + e3;
            float h0 = __bfloat162float(__float2bfloat16(e0));
            float h1 = __bfloat162float(__float2bfloat16(e1));
            float h2 = __bfloat162float(__float2bfloat16(e2));
            float h3 = __bfloat162float(__float2bfloat16(e3));
            pH[j][0] = pk2(e0, e1);
            pH[j][1] = pk2(e2, e3);
            pL[j][0] = pk2(e0 - h0, e1 - h1);
            pL[j][1] = pk2(e2 - h2, e3 - h3);
        }

        #pragma unroll
        for (int kk = 0; kk < 2; kk++) {
            const uint32_t ah0 = pH[2 * kk][0], ah1 = pH[2 * kk][1];
            const uint32_t ah2 = pH[2 * kk + 1][0], ah3 = pH[2 * kk + 1][1];
            const uint32_t al0r = pL[2 * kk][0], al1r = pL[2 * kk][1];
            const uint32_t al2r = pL[2 * kk + 1][0], al3r = pL[2 * kk + 1][1];
            #pragma unroll
            for (int t2 = 0; t2 < 8; t2++) {
                uint32_t swG = SWZ256((kk * 16 + gRow) * 256 + (2 * t2 + gCol) * 16);
                uint32_t gh0, gh1, gh2, gh3, gl0, gl1, gl2, gl3;
                LDSM_X4_T(gh0, gh1, gh2, gh3, bs + 16384 + swG);
                LDSM_X4_T(gl0, gl1, gl2, gl3, bs + 24576 + swG);
                mma16816(yacc[2 * t2],     ah0, ah1, ah2, ah3, gh0, gh1);
                mma16816(yacc[2 * t2],     ah0, ah1, ah2, ah3, gl0, gl1);
                mma16816(yacc[2 * t2],     al0r, al1r, al2r, al3r, gh0, gh1);
                mma16816(yacc[2 * t2 + 1], ah0, ah1, ah2, ah3, gh2, gh3);
                mma16816(yacc[2 * t2 + 1], ah0, ah1, ah2, ah3, gl2, gl3);
                mma16816(yacc[2 * t2 + 1], al0r, al1r, al2r, al3r, gh2, gh3);
            }
        }
    }

    rl0 += __shfl_xor_sync(0xffffffffu, rl0, 1);
    rl0 += __shfl_xor_sync(0xffffffffu, rl0, 2);
    rl1 += __shfl_xor_sync(0xffffffffu, rl1, 1);
    rl1 += __shfl_xor_sync(0xffffffffu, rl1, 2);
    const float inv0 = 1.f / rl0;
    const float inv1 = 1.f / rl1;
    const int n0 = nBlock + wid * 16 + (lane >> 2);
    const int cB = (lane & 3) * 2;
    #pragma unroll
    for (int t = 0; t < 16; t++) {
        const int ci = t * 8 + cB;
        float c0 = yacc[t][0] * inv0, c1 = yacc[t][1] * inv0;
        float c2 = yacc[t][2] * inv1, c3 = yacc[t][3] * inv1;
        __nv_bfloat16 h0, h1, h2, h3, l0, l1, l2, l3;
        split2(c0, h0, l0); split2(c1, h1, l1);
        split2(c2, h2, l2); split2(c3, h3, l3);
        const long o0 = ((long)b * NN + n0) * CI + ci;
        const long o1 = ((long)b * NN + n0 + 8) * CI + ci;
        *(__nv_bfloat162*)&g_y_hi[o0] = __nv_bfloat162(h0, h1);
        *(__nv_bfloat162*)&g_y_lo[o0] = __nv_bfloat162(l0, l1);
        *(__nv_bfloat162*)&g_y_hi[o1] = __nv_bfloat162(h2, h3);
        *(__nv_bfloat162*)&g_y_lo[o1] = __nv_bfloat162(l2, l3);
    }
}

// ---------------- x transpose + hi/lo convert ----------------------------------
__global__ __launch_bounds__(256) void transpose_x(const float* __restrict__ x) {
    __shared__ float t[32][33];
    const int b = blockIdx.z;
    const int n0 = blockIdx.x * 32, c0 = blockIdx.y * 32;
    const int tx = threadIdx.x, ty = threadIdx.y;
    #pragma unroll
    for (int i = ty; i < 32; i += 8)
        t[i][tx] = x[((long)b * CC + c0 + i) * NN + n0 + tx];
    __syncthreads();
    #pragma unroll
    for (int i = ty; i < 32; i += 8) {
        float v = t[tx][i];
        __nv_bfloat16 h, l;
        split2(v, h, l);
        const long o = ((long)b * NN + n0 + i) * CC + c0 + tx;
        g_xT_hi[o] = h;
        g_xT_lo[o] = l;
    }
}

// ---------------- weight convert ------------------------------------------------
__global__ __launch_bounds__(256) void convert_w(
    const float* __restrict__ tw, const float* __restrict__ pw, const float* __restrict__ gw,
    const float* __restrict__ tb, const float* __restrict__ pb, const float* __restrict__ gb,
    const float* __restrict__ Ww)
{
    const int i = blockIdx.x * 256 + threadIdx.x;
    const int TOT1 = 384 * CC;
    const int TOT2 = TOT1 + CC * CI;
    if (i < TOT1) {
        int o = i / CC, c = i % CC;
        float v = (o < 128) ? tw[o * CC + c] : (o < 256) ? pw[(o - 128) * CC + c] : gw[(o - 256) * CC + c];
        __nv_bfloat16 h, l; split2(v, h, l);
        g_w_hi[i] = h; g_w_lo[i] = l;
    } else if (i < TOT2) {
        float v = Ww[i - TOT1];
        __nv_bfloat16 h, l; split2(v, h, l);
        g_w_hi[i] = h; g_w_lo[i] = l;
    }
    if (i < 384)
        g_bias384[i] = (i < 128) ? tb[i] : (i < 256) ? pb[i - 128] : gb[i - 256];
}

// ---------------- 2x2 maxpool (both outputs [m][ci], coalesced) -----------------
__device__ __forceinline__ void ld4bf(const __nv_bfloat16* p, float* out) {
    uint2 u = *(const uint2*)p;
    __nv_bfloat162 a = *(__nv_bfloat162*)&u.x;
    __nv_bfloat162 bq = *(__nv_bfloat162*)&u.y;
    out[0] = __bfloat162float(a.x); out[1] = __bfloat162float(a.y);
    out[2] = __bfloat162float(bq.x); out[3] = __bfloat162float(bq.y);
}

__global__ __launch_bounds__(256) void pool_kernel() {
    const int i = blockIdx.x * 256 + threadIdx.x;   // BB*MM*32
    if (i >= BB * MM * 32) return;
    const int c4 = (i & 31) << 2;
    const int m  = (i >> 5) & (MM - 1);
    const int b  = i >> 15;
    const int hp = m >> 5, wp = m & 31;
    const int n0 = hp * 128 + wp * 2;
    const long rb = (long)b * NN;
    const long o = ((long)b * MM + m) * CI + c4;

    #pragma unroll
    for (int which = 0; which < 2; which++) {
        const int col = (which == 0 ? 128 : 256) + c4;
        float mx[4] = {-1e30f, -1e30f, -1e30f, -1e30f};
        #pragma unroll
        for (int rr = 0; rr < 4; rr++) {
            const int n = n0 + (rr & 1) + (rr >> 1) * 64;
            const long base = (rb + n) * 384 + col;
            float vh[4], vl[4];
            ld4bf(&g_o3_hi[base], vh);
            ld4bf(&g_o3_lo[base], vl);
            #pragma unroll
            for (int e = 0; e < 4; e++) mx[e] = fmaxf(mx[e], vh[e] + vl[e]);
        }
        __nv_bfloat16 h[4], l[4];
        #pragma unroll
        for (int e = 0; e < 4; e++) split2(mx[e], h[e], l[e]);
        __nv_bfloat16* dh = (which == 0) ? g_phi_hi : g_gm_hi;
        __nv_bfloat16* dl = (which == 0) ? g_phi_lo : g_gm_lo;
        *(__nv_bfloat162*)&dh[o]     = __nv_bfloat162(h[0], h[1]);
        *(__nv_bfloat162*)&dh[o + 2] = __nv_bfloat162(h[2], h[3]);
        *(__nv_bfloat162*)&dl[o]     = __nv_bfloat162(l[0], l[1]);
        *(__nv_bfloat162*)&dl[o + 2] = __nv_bfloat162(l[2], l[3]);
    }
}

// ---------------- BN reduce from K4 partials (deterministic) -------------------
__global__ __launch_bounds__(256) void bn_reduce(const float* __restrict__ gamma,
                                                 const float* __restrict__ beta) {
    const int c = blockIdx.x;
    const int t = threadIdx.x;
    double s = 0.0, q = 0.0;
    #pragma unroll
    for (int i = t; i < 1024; i += 256) {
        s += (double)g_part_s[c * 1024 + i];
        q += (double)g_part_q[c * 1024 + i];
    }
    __shared__ double ss[256], sz[256];
    ss[t] = s; sz[t] = q;
    __syncthreads();
    for (int st = 128; st; st >>= 1) {
        if (t < st) { ss[t] += ss[t + st]; sz[t] += sz[t + st]; }
        __syncthreads();
    }
    if (t == 0) {
        const double cnt = 1.0 / (double)(BB * NN);
        const double mean = ss[0] * cnt;
        const double var  = sz[0] * cnt - mean * mean;
        const double inv  = 1.0 / sqrt(var + 1e-5);
        const float sc = gamma[c] * (float)inv;
        g_scale[c] = sc;
        g_shift[c] = beta[c] - (float)mean * sc;
    }
}

// ---------------- apply BN + residual ------------------------------------------
__global__ __launch_bounds__(256) void final_kernel(const float* __restrict__ x,
                                                    float* __restrict__ out) {
    const long i = (long)blockIdx.x * 256 + threadIdx.x;
    const long e = i << 2;
    const int c = (int)((e >> 12) & (CC - 1));
    const float sc = g_scale[c], sh = g_shift[c];
    float4 wy = ((const float4*)g_wy)[i];
    float4 xv = ((const float4*)x)[i];
    float4 o;
    o.x = fmaf(wy.x, sc, sh) + xv.x;
    o.y = fmaf(wy.y, sc, sh) + xv.y;
    o.z = fmaf(wy.z, sc, sh) + xv.z;
    o.w = fmaf(wy.w, sc, sh) + xv.w;
    ((float4*)out)[i] = o;
}

// ------------------------------------------------------------------------------
extern "C" void kernel_launch(void* const* d_in, const int* in_sizes, int n_in,
                              void* d_out, int out_size) {
    (void)in_sizes; (void)n_in; (void)out_size;
    const float* x     = (const float*)d_in[0];
    const float* tw    = (const float*)d_in[1];
    const float* tb    = (const float*)d_in[2];
    const float* pw    = (const float*)d_in[3];
    const float* pb    = (const float*)d_in[4];
    const float* gw    = (const float*)d_in[5];
    const float* gb    = (const float*)d_in[6];
    const float* Ww    = (const float*)d_in[7];
    const float* Wb    = (const float*)d_in[8];
    const float* gamma = (const float*)d_in[9];
    const float* beta  = (const float*)d_in[10];
    float* out = (float*)d_out;

    __nv_bfloat16 *xTh, *xTl, *wh, *wl, *o3h, *o3l, *yh, *yl;
    float *wy, *bias384;
    cudaGetSymbolAddress((void**)&xTh, g_xT_hi);  cudaGetSymbolAddress((void**)&xTl, g_xT_lo);
    cudaGetSymbolAddress((void**)&wh,  g_w_hi);   cudaGetSymbolAddress((void**)&wl,  g_w_lo);
    cudaGetSymbolAddress((void**)&o3h, g_o3_hi);  cudaGetSymbolAddress((void**)&o3l, g_o3_lo);
    cudaGetSymbolAddress((void**)&yh,  g_y_hi);   cudaGetSymbolAddress((void**)&yl,  g_y_lo);
    cudaGetSymbolAddress((void**)&wy,  g_wy);
    cudaGetSymbolAddress((void**)&bias384, g_bias384);

    cudaFuncSetAttribute(gemm_bf16<2, true,  false>, cudaFuncAttributeMaxDynamicSharedMemorySize, SMEM_GEMM_BYTES);
    cudaFuncSetAttribute(gemm_bf16<1, false, true >, cudaFuncAttributeMaxDynamicSharedMemorySize, SMEM_GEMM_BYTES);
    cudaFuncSetAttribute(attn_kernel, cudaFuncAttributeMaxDynamicSharedMemorySize, ATT_SMEM);

    // P1: convert weights + biases
    convert_w<<<(384 * CC + CC * CI + 255) / 256, 256>>>(tw, pw, gw, tb, pb, gb, Ww);
    // P2: transpose + convert x -> xT [b][n][c]
    transpose_x<<<dim3(NN / 32, CC / 32, BB), dim3(32, 8)>>>(x);

    // K1: o3[b][n][o<384] = xT[n][c] . wcat[o][c]  (col bias), out bf16 hi/lo
    gemm_bf16<2, true, false><<<dim3(3, 32, BB), 256, SMEM_GEMM_BYTES>>>(
        xTh, xTl, wh, wl, bias384, nullptr, o3h, o3l,
        CC, CC, 384, CC, (long)NN * CC, 0, (long)NN * 384);

    // K2: maxpool -> phi [m][ci], gm [m][ci]
    pool_kernel<<<(BB * MM * 32 + 255) / 256, 256>>>();

    // K3: fused theta.phi^T -> exp -> .g  ==> y [b][n][ci] bf16 hi/lo
    attn_kernel<<<dim3(NN / 64, BB), 128, ATT_SMEM>>>();

    // K4: wy[c][n] = Ww[c][ci] . y[n][ci]  (row bias Wb) + BN partial sums
    gemm_bf16<1, false, true><<<dim3(NN / 128, CC / 128, BB), 256, SMEM_GEMM_BYTES>>>(
        wh + 384 * CC, wl + 384 * CC, yh, yl, Wb, wy, nullptr, nullptr,
        CI, CI, NN, CI, 0, (long)NN * CI, (long)CC * NN);

    // K5: BN reduce from partials
    bn_reduce<<<CC, 256>>>(gamma, beta);

    // K6: apply BN + residual
    final_kernel<<<(BB * CC * NN) / 4 / 256, 256>>>(x, out);
}